// round 1
// baseline (speedup 1.0000x reference)
#include <cuda_runtime.h>
#include <math.h>

// Problem constants
#define B        32
#define NOBJ_PER 64          // 8x8 objects per image
#define NOBJ     (B * NOBJ_PER)   // 2048
#define H_IMG    128
#define W_IMG    128
#define C        32
#define H_OUT    32
#define W_OUT    32
#define OUT_ELEMS (B * NOBJ_PER * H_OUT * W_OUT * C)   // 67,108,864

// Per-object affine params: {sx, sy, tx, ty}
__device__ float4 g_params[NOBJ];

// ---------------------------------------------------------------------------
// Prep: 2048 threads. Compute affine params (sigmoid/tanh/bias) once per
// object, write bbox-mask part of the output.
// ---------------------------------------------------------------------------
__global__ void stn_prep_kernel(const float* __restrict__ z_where,
                                float* __restrict__ bbox_out) {
    int t = blockIdx.x * blockDim.x + threadIdx.x;
    if (t >= NOBJ) return;

    int p     = t & 63;        // object index within image
    int i_obj = p >> 3;        // 0..7
    int j_obj = p & 7;         // 0..7

    float4 zv = ((const float4*)z_where)[t];

    // sx = 0.5*sigmoid(z0), sy = 0.5*sigmoid(z1)
    float sx = 0.5f / (1.0f + expf(-zv.x));
    float sy = 0.5f / (1.0f + expf(-zv.y));

    // cr = 0.5 -> bias = 1.5*idx/7 - 0.75
    float bias_tx = 1.5f * (float)j_obj * (1.0f / 7.0f) - 0.75f;
    float bias_ty = 1.5f * (float)i_obj * (1.0f / 7.0f) - 0.75f;

    float tx = 0.5f * tanhf(zv.z) + bias_tx;
    float ty = 0.5f * tanhf(zv.w) + bias_ty;

    g_params[t] = make_float4(sx, sy, tx, ty);

    // bbox mask: [bty-bh, btx-bw, bty+bh, btx+bw]
    float bh  = sy * 0.5f;
    float bw  = sx * 0.5f;
    float bty = (ty + 1.0f) * 0.5f;
    float btx = (tx + 1.0f) * 0.5f;
    ((float4*)bbox_out)[t] = make_float4(bty - bh, btx - bw, bty + bh, btx + bw);
}

// ---------------------------------------------------------------------------
// Main: one thread per float4 of output (4 channels).
// t layout: c4 = t&7 (channel/4), j = (t>>3)&31, i = (t>>8)&31, obj = t>>13.
// Warp covers 4 consecutive j at one (obj,i): 4 gather LDG.128 + 1 contiguous
// STG.128 per warp. Param load is a warp-broadcast.
// ---------------------------------------------------------------------------
__global__ void __launch_bounds__(256) stn_sample_kernel(
        const float* __restrict__ x, float* __restrict__ out) {
    unsigned t   = blockIdx.x * blockDim.x + threadIdx.x;   // < 16,777,216
    unsigned c4  = t & 7u;
    unsigned j   = (t >> 3) & 31u;
    unsigned i   = (t >> 8) & 31u;
    unsigned obj = t >> 13;                                 // b*64 + p
    unsigned b   = obj >> 6;

    float4 prm = g_params[obj];    // broadcast within warp

    // grid coords: linspace(-1,1,32)
    float X = -1.0f + (float)j * (2.0f / 31.0f);
    float Y = -1.0f + (float)i * (2.0f / 31.0f);

    float gx = fmaf(prm.x, X, prm.z);   // sx*X + tx
    float gy = fmaf(prm.y, Y, prm.w);   // sy*Y + ty

    float px = 0.5f * (gx + 1.0f) * (float)(W_IMG - 1);
    float py = 0.5f * (gy + 1.0f) * (float)(H_IMG - 1);

    // floor -> +1 -> clip both -> weights from CLIPPED coords (matches ref)
    float x0f = floorf(px), y0f = floorf(py);
    float x1f = x0f + 1.0f, y1f = y0f + 1.0f;
    x0f = fminf(fmaxf(x0f, 0.0f), (float)(W_IMG - 1));
    x1f = fminf(fmaxf(x1f, 0.0f), (float)(W_IMG - 1));
    y0f = fminf(fmaxf(y0f, 0.0f), (float)(H_IMG - 1));
    y1f = fminf(fmaxf(y1f, 0.0f), (float)(H_IMG - 1));

    float wa = (x1f - px) * (y1f - py);
    float wb = (x1f - px) * (py  - y0f);
    float wc = (px - x0f) * (y1f - py);
    float wd = (px - x0f) * (py  - y0f);

    int xi0 = (int)x0f, xi1 = (int)x1f;
    int yi0 = (int)y0f, yi1 = (int)y1f;

    const float4* img = (const float4*)x;
    // float4 index: ((b*128 + y)*128 + xv)*8 + c4
    unsigned r0 = (b * (unsigned)H_IMG + (unsigned)yi0) * (unsigned)W_IMG;
    unsigned r1 = (b * (unsigned)H_IMG + (unsigned)yi1) * (unsigned)W_IMG;

    float4 Ia = __ldg(&img[(r0 + (unsigned)xi0) * 8u + c4]);   // (y0,x0)
    float4 Ic = __ldg(&img[(r0 + (unsigned)xi1) * 8u + c4]);   // (y0,x1)
    float4 Ib = __ldg(&img[(r1 + (unsigned)xi0) * 8u + c4]);   // (y1,x0)
    float4 Id = __ldg(&img[(r1 + (unsigned)xi1) * 8u + c4]);   // (y1,x1)

    float4 o;
    o.x = fmaf(wa, Ia.x, fmaf(wb, Ib.x, fmaf(wc, Ic.x, wd * Id.x)));
    o.y = fmaf(wa, Ia.y, fmaf(wb, Ib.y, fmaf(wc, Ic.y, wd * Id.y)));
    o.z = fmaf(wa, Ia.z, fmaf(wb, Ib.z, fmaf(wc, Ic.z, wd * Id.z)));
    o.w = fmaf(wa, Ia.w, fmaf(wb, Ib.w, fmaf(wc, Ic.w, wd * Id.w)));

    ((float4*)out)[t] = o;
}

extern "C" void kernel_launch(void* const* d_in, const int* in_sizes, int n_in,
                              void* d_out, int out_size) {
    const float* x = (const float*)d_in[0];        // (32,128,128,32) f32
    const float* z = (const float*)d_in[1];        // (32,8,8,4) f32
    float* out = (float*)d_out;                    // 67,108,864 + 8,192 f32

    // Prep: params + bbox mask (written at offset OUT_ELEMS)
    stn_prep_kernel<<<(NOBJ + 255) / 256, 256>>>(z, out + OUT_ELEMS);

    // Main sample: 16,777,216 threads (one per output float4)
    const unsigned total_f4 = OUT_ELEMS / 4;       // 16,777,216
    stn_sample_kernel<<<total_f4 / 256, 256>>>(x, out);
}

// round 4
// speedup vs baseline: 1.2143x; 1.2143x over previous
#include <cuda_runtime.h>
#include <math.h>

// Problem constants
#define B        32
#define NOBJ_PER 64
#define NOBJ     (B * NOBJ_PER)       // 2048
#define H_IMG    128
#define W_IMG    128
#define C        32
#define H_OUT    32
#define W_OUT    32
#define OUT_ELEMS (B * NOBJ_PER * H_OUT * W_OUT * C)   // 67,108,864

// Per-object affine params: {sx, sy, tx, ty}
__device__ float4 g_params[NOBJ];

// ---------------------------------------------------------------------------
// Prep: 2048 threads. Params + bbox mask.
// ---------------------------------------------------------------------------
__global__ void stn_prep_kernel(const float* __restrict__ z_where,
                                float* __restrict__ bbox_out) {
    int t = blockIdx.x * blockDim.x + threadIdx.x;
    if (t >= NOBJ) return;

    int p     = t & 63;
    int i_obj = p >> 3;
    int j_obj = p & 7;

    float4 zv = ((const float4*)z_where)[t];

    float sx = 0.5f / (1.0f + expf(-zv.x));
    float sy = 0.5f / (1.0f + expf(-zv.y));

    float bias_tx = 1.5f * (float)j_obj * (1.0f / 7.0f) - 0.75f;
    float bias_ty = 1.5f * (float)i_obj * (1.0f / 7.0f) - 0.75f;

    float tx = 0.5f * tanhf(zv.z) + bias_tx;
    float ty = 0.5f * tanhf(zv.w) + bias_ty;

    g_params[t] = make_float4(sx, sy, tx, ty);

    float bh  = sy * 0.5f;
    float bw  = sx * 0.5f;
    float bty = (ty + 1.0f) * 0.5f;
    float btx = (tx + 1.0f) * 0.5f;
    ((float4*)bbox_out)[t] = make_float4(bty - bh, btx - bw, bty + bh, btx + bw);
}

// ---------------------------------------------------------------------------
// Main: one thread per TWO output float4s (pixels j and j+16 of one row).
// u layout: c4 = u&7, j = (u>>3)&15, i = (u>>7)&31, obj = u>>12.
// 8 independent LDG.128 in flight per thread; y-weights shared between the
// two pixels; both STG.128 are contiguous 512B per warp.
// ---------------------------------------------------------------------------
__global__ void __launch_bounds__(256) stn_sample_kernel(
        const float* __restrict__ x, float* __restrict__ out) {
    unsigned u   = blockIdx.x * blockDim.x + threadIdx.x;   // < 8,388,608
    unsigned c4  = u & 7u;
    unsigned j   = (u >> 3) & 15u;
    unsigned i   = (u >> 7) & 31u;
    unsigned obj = u >> 12;
    unsigned b   = obj >> 6;

    float4 prm = g_params[obj];

    const float STEP = 2.0f / 31.0f;
    float X1 = -1.0f + (float)j * STEP;
    float X2 = X1 + 16.0f * STEP;
    float Y  = -1.0f + (float)i * STEP;

    float gx1 = fmaf(prm.x, X1, prm.z);
    float gx2 = fmaf(prm.x, X2, prm.z);
    float gy  = fmaf(prm.y, Y,  prm.w);

    float px1 = 0.5f * (gx1 + 1.0f) * (float)(W_IMG - 1);
    float px2 = 0.5f * (gx2 + 1.0f) * (float)(W_IMG - 1);
    float py  = 0.5f * (gy  + 1.0f) * (float)(H_IMG - 1);

    // ---- y side (shared by both pixels) ----
    float y0f = floorf(py);
    float y1f = y0f + 1.0f;
    y0f = fminf(fmaxf(y0f, 0.0f), (float)(H_IMG - 1));
    y1f = fminf(fmaxf(y1f, 0.0f), (float)(H_IMG - 1));
    float wy0 = (y1f - py);
    float wy1 = (py  - y0f);
    int yi0 = (int)y0f, yi1 = (int)y1f;

    // ---- x side, pixel 1 ----
    float x0f1 = floorf(px1);
    float x1f1 = x0f1 + 1.0f;
    x0f1 = fminf(fmaxf(x0f1, 0.0f), (float)(W_IMG - 1));
    x1f1 = fminf(fmaxf(x1f1, 0.0f), (float)(W_IMG - 1));
    float wx0a = (x1f1 - px1);
    float wx1a = (px1  - x0f1);
    int xi0a = (int)x0f1, xi1a = (int)x1f1;

    // ---- x side, pixel 2 ----
    float x0f2 = floorf(px2);
    float x1f2 = x0f2 + 1.0f;
    x0f2 = fminf(fmaxf(x0f2, 0.0f), (float)(W_IMG - 1));
    x1f2 = fminf(fmaxf(x1f2, 0.0f), (float)(W_IMG - 1));
    float wx0b = (x1f2 - px2);
    float wx1b = (px2  - x0f2);
    int xi0b = (int)x0f2, xi1b = (int)x1f2;

    const float4* img = (const float4*)x;
    // Row bases already scaled to float4 granularity, with c4 folded in.
    unsigned r0 = ((b * (unsigned)H_IMG + (unsigned)yi0) * (unsigned)W_IMG) * 8u + c4;
    unsigned r1 = ((b * (unsigned)H_IMG + (unsigned)yi1) * (unsigned)W_IMG) * 8u + c4;

    // ---- 8 independent gathers, all issued before any use ----
    float4 A1 = __ldg(&img[r0 + (unsigned)xi0a * 8u]);  // p1 (y0,x0)
    float4 C1 = __ldg(&img[r0 + (unsigned)xi1a * 8u]);  // p1 (y0,x1)
    float4 B1 = __ldg(&img[r1 + (unsigned)xi0a * 8u]);  // p1 (y1,x0)
    float4 D1 = __ldg(&img[r1 + (unsigned)xi1a * 8u]);  // p1 (y1,x1)
    float4 A2 = __ldg(&img[r0 + (unsigned)xi0b * 8u]);  // p2 (y0,x0)
    float4 C2 = __ldg(&img[r0 + (unsigned)xi1b * 8u]);  // p2 (y0,x1)
    float4 B2 = __ldg(&img[r1 + (unsigned)xi0b * 8u]);  // p2 (y1,x0)
    float4 D2 = __ldg(&img[r1 + (unsigned)xi1b * 8u]);  // p2 (y1,x1)

    // ---- blend pixel 1 ----
    float wa = wx0a * wy0, wb = wx0a * wy1, wc = wx1a * wy0, wd = wx1a * wy1;
    float4 o1;
    o1.x = fmaf(wa, A1.x, fmaf(wb, B1.x, fmaf(wc, C1.x, wd * D1.x)));
    o1.y = fmaf(wa, A1.y, fmaf(wb, B1.y, fmaf(wc, C1.y, wd * D1.y)));
    o1.z = fmaf(wa, A1.z, fmaf(wb, B1.z, fmaf(wc, C1.z, wd * D1.z)));
    o1.w = fmaf(wa, A1.w, fmaf(wb, B1.w, fmaf(wc, C1.w, wd * D1.w)));

    // ---- blend pixel 2 ----
    float we = wx0b * wy0, wf = wx0b * wy1, wg = wx1b * wy0, wh = wx1b * wy1;
    float4 o2;
    o2.x = fmaf(we, A2.x, fmaf(wf, B2.x, fmaf(wg, C2.x, wh * D2.x)));
    o2.y = fmaf(we, A2.y, fmaf(wf, B2.y, fmaf(wg, C2.y, wh * D2.y)));
    o2.z = fmaf(we, A2.z, fmaf(wf, B2.z, fmaf(wg, C2.z, wh * D2.z)));
    o2.w = fmaf(we, A2.w, fmaf(wf, B2.w, fmaf(wg, C2.w, wh * D2.w)));

    // ---- stores: pixel index = ((obj*32 + i)*32 + j)*8 + c4 ----
    unsigned t1 = ((obj * 32u + i) * 32u + j) * 8u + c4;
    ((float4*)out)[t1]        = o1;
    ((float4*)out)[t1 + 128u] = o2;   // j+16 -> +16*8 float4s
}

extern "C" void kernel_launch(void* const* d_in, const int* in_sizes, int n_in,
                              void* d_out, int out_size) {
    const float* x = (const float*)d_in[0];
    const float* z = (const float*)d_in[1];
    float* out = (float*)d_out;

    stn_prep_kernel<<<(NOBJ + 255) / 256, 256>>>(z, out + OUT_ELEMS);

    const unsigned total_threads = OUT_ELEMS / 8;   // 8,388,608
    stn_sample_kernel<<<total_threads / 256, 256>>>(x, out);
}